// round 1
// baseline (speedup 1.0000x reference)
#include <cuda_runtime.h>
#include <cuda_bf16.h>

// out[row] = (sum over F elements of x[row, :]) * sum(coeffs)
// x: [R, F] fp32 contiguous, F assumed divisible by 4.
// One block per row; 256 threads; each thread grid-strides float4s across the row.
__global__ void spline_rowsum_kernel(const float* __restrict__ x,
                                     const float* __restrict__ coeffs,
                                     int ncoef,
                                     int f_vec4,            // F / 4
                                     float* __restrict__ out) {
    const int row = blockIdx.x;
    const float4* __restrict__ xp =
        reinterpret_cast<const float4*>(x) + (size_t)row * f_vec4;

    float s = 0.0f;
    for (int i = threadIdx.x; i < f_vec4; i += blockDim.x) {
        float4 v = xp[i];
        s += (v.x + v.y) + (v.z + v.w);
    }

    // warp reduce
    #pragma unroll
    for (int o = 16; o > 0; o >>= 1)
        s += __shfl_xor_sync(0xffffffffu, s, o);

    __shared__ float ws[8];
    const int lane = threadIdx.x & 31;
    const int w = threadIdx.x >> 5;
    if (lane == 0) ws[w] = s;
    __syncthreads();

    if (threadIdx.x == 0) {
        float t = 0.0f;
        const int nwarps = blockDim.x >> 5;
        #pragma unroll
        for (int i = 0; i < 8; i++)
            if (i < nwarps) t += ws[i];

        float cs = 0.0f;
        for (int i = 0; i < ncoef; i++) cs += coeffs[i];   // 10 elems, L2-resident

        out[row] = t * cs;
    }
}

extern "C" void kernel_launch(void* const* d_in, const int* in_sizes, int n_in,
                              void* d_out, int out_size) {
    const float* x      = (const float*)d_in[0];
    const float* coeffs = (const float*)d_in[1];
    float*       out    = (float*)d_out;

    const int rows  = out_size;                 // 16*4096 = 65536
    const int F     = in_sizes[0] / rows;       // 1024
    const int fvec4 = F / 4;                    // 256
    const int ncoef = in_sizes[1];              // 10

    spline_rowsum_kernel<<<rows, 256>>>(x, coeffs, ncoef, fvec4, out);
}

// round 2
// speedup vs baseline: 1.4952x; 1.4952x over previous
#include <cuda_runtime.h>
#include <cuda_bf16.h>

// out[row] = (sum over 1024 elements of x[row,:]) * sum(coeffs)
// One warp per row: 32 lanes x 8 float4 loads (fully unrolled, MLP=8),
// warp-shuffle reduce only. No smem, no block barriers.
__global__ void __launch_bounds__(256) spline_rowsum_warp_kernel(
        const float* __restrict__ x,
        const float* __restrict__ coeffs,
        int ncoef,
        int rows,
        float* __restrict__ out) {
    const int warp_global = (blockIdx.x * (blockDim.x >> 5)) + (threadIdx.x >> 5);
    if (warp_global >= rows) return;
    const int lane = threadIdx.x & 31;

    // row of 1024 floats = 256 float4; lane l takes indices l, l+32, ..., l+224
    const float4* __restrict__ xp =
        reinterpret_cast<const float4*>(x) + (size_t)warp_global * 256 + lane;

    // 8 independent loads in flight
    float4 v0 = xp[0 * 32];
    float4 v1 = xp[1 * 32];
    float4 v2 = xp[2 * 32];
    float4 v3 = xp[3 * 32];
    float4 v4 = xp[4 * 32];
    float4 v5 = xp[5 * 32];
    float4 v6 = xp[6 * 32];
    float4 v7 = xp[7 * 32];

    float s0 = (v0.x + v0.y) + (v0.z + v0.w);
    float s1 = (v1.x + v1.y) + (v1.z + v1.w);
    float s2 = (v2.x + v2.y) + (v2.z + v2.w);
    float s3 = (v3.x + v3.y) + (v3.z + v3.w);
    float s4 = (v4.x + v4.y) + (v4.z + v4.w);
    float s5 = (v5.x + v5.y) + (v5.z + v5.w);
    float s6 = (v6.x + v6.y) + (v6.z + v6.w);
    float s7 = (v7.x + v7.y) + (v7.z + v7.w);

    float s = ((s0 + s1) + (s2 + s3)) + ((s4 + s5) + (s6 + s7));

    #pragma unroll
    for (int o = 16; o > 0; o >>= 1)
        s += __shfl_xor_sync(0xffffffffu, s, o);

    if (lane == 0) {
        float cs = 0.0f;
        for (int i = 0; i < ncoef; i++) cs += coeffs[i];  // 10 elems, L2-hit
        out[warp_global] = s * cs;
    }
}

extern "C" void kernel_launch(void* const* d_in, const int* in_sizes, int n_in,
                              void* d_out, int out_size) {
    const float* x      = (const float*)d_in[0];
    const float* coeffs = (const float*)d_in[1];
    float*       out    = (float*)d_out;

    const int rows  = out_size;            // 65536
    const int ncoef = in_sizes[1];         // 10

    const int warps_per_block = 8;         // 256 threads
    const int blocks = (rows + warps_per_block - 1) / warps_per_block;  // 8192
    spline_rowsum_warp_kernel<<<blocks, 256>>>(x, coeffs, ncoef, rows, out);
}